// round 2
// baseline (speedup 1.0000x reference)
#include <cuda_runtime.h>

namespace {

constexpr int B  = 4096;
constexpr int T  = 1000;
constexpr int IN = 3;
constexpr int H  = 10;

constexpr int WARPS = 2;            // warps per block
constexpr int EPW   = 3;            // elements per warp (30 active lanes)
constexpr int EPB   = WARPS * EPW;  // 6 elements per block
constexpr int NBLK  = (B + EPB - 1) / EPB;  // 683
constexpr int RS    = 12;           // padded row stride (floats), 48B = 16B-aligned

__device__ __forceinline__ float sigf(float v) {
    // 1/(1+e^-v); saturates correctly for |v| large
    return __fdividef(1.0f, 1.0f + __expf(-v));
}
__device__ __forceinline__ float tanhf_fast(float v) {
    // 1 - 2/(e^{2v}+1); exact limits at +-inf
    return 1.0f - __fdividef(2.0f, __expf(2.0f * v) + 1.0f);
}

__device__ __forceinline__ void load10(const float* __restrict__ p, float* v) {
    float4 a = *reinterpret_cast<const float4*>(p);
    float4 b = *reinterpret_cast<const float4*>(p + 4);
    float2 c = *reinterpret_cast<const float2*>(p + 8);
    v[0]=a.x; v[1]=a.y; v[2]=a.z; v[3]=a.w;
    v[4]=b.x; v[5]=b.y; v[6]=b.z; v[7]=b.w;
    v[8]=c.x; v[9]=c.y;
}

__device__ __forceinline__ float dot10(const float* __restrict__ w,
                                       const float* __restrict__ v,
                                       float acc) {
    float4 a = *reinterpret_cast<const float4*>(w);
    float4 b = *reinterpret_cast<const float4*>(w + 4);
    float2 c = *reinterpret_cast<const float2*>(w + 8);
    acc = fmaf(a.x, v[0], acc); acc = fmaf(a.y, v[1], acc);
    acc = fmaf(a.z, v[2], acc); acc = fmaf(a.w, v[3], acc);
    acc = fmaf(b.x, v[4], acc); acc = fmaf(b.y, v[5], acc);
    acc = fmaf(b.z, v[6], acc); acc = fmaf(b.w, v[7], acc);
    acc = fmaf(c.x, v[8], acc); acc = fmaf(c.y, v[9], acc);
    return acc;
}

// GRU cell for layers with 10-wide input, weights from smem rows.
__device__ __forceinline__ float gru_cell(
    const float* __restrict__ wih_r, const float* __restrict__ wih_z, const float* __restrict__ wih_n,
    const float* __restrict__ whh_r, const float* __restrict__ whh_z, const float* __restrict__ whh_n,
    float br, float bz, float bxn, float bhn,
    const float* __restrict__ iv, const float* __restrict__ hv, float hown)
{
    float ar  = dot10(wih_r, iv, br);
    float az  = dot10(wih_z, iv, bz);
    float axn = dot10(wih_n, iv, bxn);
    ar  = dot10(whh_r, hv, ar);
    az  = dot10(whh_z, hv, az);
    float ahn = dot10(whh_n, hv, bhn);
    float r = sigf(ar);
    float z = sigf(az);
    float n = tanhf_fast(fmaf(r, ahn, axn));
    return n + z * (hown - n);   // (1-z)*n + z*h
}

__global__ void __launch_bounds__(WARPS * 32)
gru3_fused(const float* __restrict__ x,
           const float* __restrict__ Wih0, const float* __restrict__ Whh0,
           const float* __restrict__ bih0, const float* __restrict__ bhh0,
           const float* __restrict__ Wih1, const float* __restrict__ Whh1,
           const float* __restrict__ bih1, const float* __restrict__ bhh1,
           const float* __restrict__ Wih2, const float* __restrict__ Whh2,
           const float* __restrict__ bih2, const float* __restrict__ bhh2,
           const float* __restrict__ Wout, const float* __restrict__ bout,
           float* __restrict__ out)
{
    __shared__ __align__(16) float s_wih1[30 * RS], s_whh1[30 * RS];
    __shared__ __align__(16) float s_wih2[30 * RS], s_whh2[30 * RS];
    __shared__ __align__(16) float s_h[2][3][EPB][RS];   // [pingpong][layer][elem][unit]

    const int tid = threadIdx.x;

    // Stage layer-1/2 weights into padded smem rows.
    for (int idx = tid; idx < 300; idx += WARPS * 32) {
        int r = idx / 10, c = idx - r * 10;
        s_wih1[r * RS + c] = Wih1[idx];
        s_whh1[r * RS + c] = Whh1[idx];
        s_wih2[r * RS + c] = Wih2[idx];
        s_whh2[r * RS + c] = Whh2[idx];
    }
    for (int idx = tid; idx < 2 * 3 * EPB * RS; idx += WARPS * 32)
        (&s_h[0][0][0][0])[idx] = 0.0f;

    const int lane = tid & 31;
    const int warp = tid >> 5;
    const int g    = lane / 10;        // element slot in warp (3 for lanes 30,31)
    const int j    = lane - g * 10;    // hidden unit
    const int eb   = warp * EPW + g;   // element index within block
    const int e    = blockIdx.x * EPB + eb;
    const bool act = (lane < 30) && (e < B);

    // Layer-0 weights + all folded biases in registers.
    float w0x[3][3], w0h[3][10];
    float br0=0,bz0=0,bxn0=0,bhn0=0;
    float br1=0,bz1=0,bxn1=0,bhn1=0;
    float br2=0,bz2=0,bxn2=0,bhn2=0;
#pragma unroll
    for (int gg = 0; gg < 3; gg++) {
#pragma unroll
        for (int k = 0; k < 3;  k++) w0x[gg][k] = 0.0f;
#pragma unroll
        for (int k = 0; k < 10; k++) w0h[gg][k] = 0.0f;
    }
    if (act) {
#pragma unroll
        for (int gg = 0; gg < 3; gg++) {
            int row = gg * 10 + j;
#pragma unroll
            for (int k = 0; k < 3;  k++) w0x[gg][k] = Wih0[row * 3  + k];
#pragma unroll
            for (int k = 0; k < 10; k++) w0h[gg][k] = Whh0[row * 10 + k];
        }
        br0 = bih0[j] + bhh0[j];  bz0 = bih0[10+j] + bhh0[10+j];
        bxn0 = bih0[20+j];        bhn0 = bhh0[20+j];
        br1 = bih1[j] + bhh1[j];  bz1 = bih1[10+j] + bhh1[10+j];
        bxn1 = bih1[20+j];        bhn1 = bhh1[20+j];
        br2 = bih2[j] + bhh2[j];  bz2 = bih2[10+j] + bhh2[10+j];
        bxn2 = bih2[20+j];        bhn2 = bhh2[20+j];
    }
    __syncthreads();

    // Per-lane smem weight row pointers (loop-invariant).
    const float* wih1_r = s_wih1 + j * RS;
    const float* wih1_z = s_wih1 + (10 + j) * RS;
    const float* wih1_n = s_wih1 + (20 + j) * RS;
    const float* whh1_r = s_whh1 + j * RS;
    const float* whh1_z = s_whh1 + (10 + j) * RS;
    const float* whh1_n = s_whh1 + (20 + j) * RS;
    const float* wih2_r = s_wih2 + j * RS;
    const float* wih2_z = s_wih2 + (10 + j) * RS;
    const float* wih2_n = s_wih2 + (20 + j) * RS;
    const float* whh2_r = s_whh2 + j * RS;
    const float* whh2_z = s_whh2 + (10 + j) * RS;
    const float* whh2_n = s_whh2 + (20 + j) * RS;

    const float* xe = x + (long)e * (T * IN);
    float xa0 = 0.f, xa1 = 0.f, xa2 = 0.f;
    if (act) { xa0 = xe[0]; xa1 = xe[1]; xa2 = xe[2]; }

    float myh0 = 0.f, myh1 = 0.f, myh2 = 0.f;

    for (int t = 0; t < T; ++t) {
        const int ob = t & 1;      // read buffer (h at t-1)
        const int nb = ob ^ 1;     // write buffer (h at t)

        // Prefetch next timestep's x (hides DRAM/L2 latency under compute).
        float xb0 = 0.f, xb1 = 0.f, xb2 = 0.f;
        if (act) {
            int tn = (t + 1 < T) ? (t + 1) : t;
            const float* p = xe + tn * IN;
            xb0 = p[0]; xb1 = p[1]; xb2 = p[2];
        }

        // ---- layer 0 (input width 3, weights in registers) ----
        if (act) {
            float hv[10];
            load10(&s_h[ob][0][eb][0], hv);
            float ar  = fmaf(w0x[0][0], xa0, fmaf(w0x[0][1], xa1, fmaf(w0x[0][2], xa2, br0)));
            float az  = fmaf(w0x[1][0], xa0, fmaf(w0x[1][1], xa1, fmaf(w0x[1][2], xa2, bz0)));
            float axn = fmaf(w0x[2][0], xa0, fmaf(w0x[2][1], xa1, fmaf(w0x[2][2], xa2, bxn0)));
            float ahn = bhn0;
#pragma unroll
            for (int k = 0; k < 10; k++) {
                ar  = fmaf(w0h[0][k], hv[k], ar);
                az  = fmaf(w0h[1][k], hv[k], az);
                ahn = fmaf(w0h[2][k], hv[k], ahn);
            }
            float r = sigf(ar);
            float z = sigf(az);
            float n = tanhf_fast(fmaf(r, ahn, axn));
            myh0 = n + z * (myh0 - n);
            s_h[nb][0][eb][j] = myh0;
        }
        __syncwarp();

        // ---- layer 1 ----
        if (act) {
            float iv[10], hv[10];
            load10(&s_h[nb][0][eb][0], iv);
            load10(&s_h[ob][1][eb][0], hv);
            myh1 = gru_cell(wih1_r, wih1_z, wih1_n, whh1_r, whh1_z, whh1_n,
                            br1, bz1, bxn1, bhn1, iv, hv, myh1);
            s_h[nb][1][eb][j] = myh1;
        }
        __syncwarp();

        // ---- layer 2 ----
        if (act) {
            float iv[10], hv[10];
            load10(&s_h[nb][1][eb][0], iv);
            load10(&s_h[ob][2][eb][0], hv);
            myh2 = gru_cell(wih2_r, wih2_z, wih2_n, whh2_r, whh2_z, whh2_n,
                            br2, bz2, bxn2, bhn2, iv, hv, myh2);
            s_h[nb][2][eb][j] = myh2;
        }
        __syncwarp();

        xa0 = xb0; xa1 = xb1; xa2 = xb2;
    }

    // Output head: out[e] = Wout . h2_final + bout   (final h2 lives in buffer T&1 = 0)
    if (act && j == 0) {
        const float* hp = &s_h[T & 1][2][eb][0];
        float acc = bout[0];
#pragma unroll
        for (int k = 0; k < 10; k++) acc = fmaf(Wout[k], hp[k], acc);
        out[e] = acc;
    }
}

} // namespace

extern "C" void kernel_launch(void* const* d_in, const int* in_sizes, int n_in,
                              void* d_out, int out_size) {
    const float* x    = (const float*)d_in[0];
    const float* Wih0 = (const float*)d_in[1];
    const float* Whh0 = (const float*)d_in[2];
    const float* bih0 = (const float*)d_in[3];
    const float* bhh0 = (const float*)d_in[4];
    const float* Wih1 = (const float*)d_in[5];
    const float* Whh1 = (const float*)d_in[6];
    const float* bih1 = (const float*)d_in[7];
    const float* bhh1 = (const float*)d_in[8];
    const float* Wih2 = (const float*)d_in[9];
    const float* Whh2 = (const float*)d_in[10];
    const float* bih2 = (const float*)d_in[11];
    const float* bhh2 = (const float*)d_in[12];
    const float* Wout = (const float*)d_in[13];
    const float* bout = (const float*)d_in[14];
    float* out = (float*)d_out;

    gru3_fused<<<NBLK, WARPS * 32>>>(x, Wih0, Whh0, bih0, bhh0,
                                     Wih1, Whh1, bih1, bhh1,
                                     Wih2, Whh2, bih2, bhh2,
                                     Wout, bout, out);
}

// round 3
// speedup vs baseline: 1.0899x; 1.0899x over previous
#include <cuda_runtime.h>

namespace {

using u64 = unsigned long long;

constexpr int B  = 4096;
constexpr int T  = 1000;
constexpr int IN = 3;

constexpr int WARPS = 2;            // warps per block
constexpr int EPW   = 3;            // elements per warp (30 active lanes)
constexpr int EPB   = WARPS * EPW;  // 6 elements per block
constexpr int NBLK  = (B + EPB - 1) / EPB;  // 683
constexpr int RS    = 12;           // padded row stride (floats), 48B (16B-aligned rows)

// ---- packed f32x2 helpers (Blackwell FFMA2 path) ----
__device__ __forceinline__ u64 fma2(u64 a, u64 b, u64 c) {
    u64 d;
    asm("fma.rn.f32x2 %0, %1, %2, %3;" : "=l"(d) : "l"(a), "l"(b), "l"(c));
    return d;
}
__device__ __forceinline__ u64 pack2(float lo, float hi) {
    u64 d;
    asm("mov.b64 %0, {%1, %2};" : "=l"(d) : "f"(lo), "f"(hi));
    return d;
}
__device__ __forceinline__ float hsum2(u64 v) {
    float lo, hi;
    asm("mov.b64 {%0, %1}, %2;" : "=f"(lo), "=f"(hi) : "l"(v));
    return lo + hi;
}

__device__ __forceinline__ float sigf(float v) {
    return __fdividef(1.0f, 1.0f + __expf(-v));
}
__device__ __forceinline__ float tanhf_fast(float v) {
    return 1.0f - __fdividef(2.0f, __expf(2.0f * v) + 1.0f);
}

// Load a 10-float smem row (16B-aligned, RS=12 padding) as 5 packed f32x2 values.
__device__ __forceinline__ void load10p(const float* __restrict__ p, u64* v) {
    ulonglong2 a = *reinterpret_cast<const ulonglong2*>(p);
    ulonglong2 b = *reinterpret_cast<const ulonglong2*>(p + 4);
    v[0] = a.x; v[1] = a.y; v[2] = b.x; v[3] = b.y;
    v[4] = *reinterpret_cast<const u64*>(p + 8);
}

// GRU cell for 10-wide input layers; all weights packed in registers.
__device__ __forceinline__ float cell(
    const u64 (&wi)[3][5], const u64 (&wh)[3][5],
    u64 bR, u64 bZ, u64 bXN, u64 bHN,
    const u64* __restrict__ iv, const u64* __restrict__ hv, float h)
{
    u64 aR = bR, aZ = bZ, aXN = bXN, aHN = bHN;
#pragma unroll
    for (int k = 0; k < 5; k++) {
        aR  = fma2(wi[0][k], iv[k], aR);
        aZ  = fma2(wi[1][k], iv[k], aZ);
        aXN = fma2(wi[2][k], iv[k], aXN);
    }
#pragma unroll
    for (int k = 0; k < 5; k++) {
        aR  = fma2(wh[0][k], hv[k], aR);
        aZ  = fma2(wh[1][k], hv[k], aZ);
        aHN = fma2(wh[2][k], hv[k], aHN);
    }
    float r = sigf(hsum2(aR));
    float z = sigf(hsum2(aZ));
    float n = tanhf_fast(fmaf(r, hsum2(aHN), hsum2(aXN)));
    return n + z * (h - n);
}

__global__ void __launch_bounds__(WARPS * 32)
gru3_fused(const float* __restrict__ x,
           const float* __restrict__ Wih0, const float* __restrict__ Whh0,
           const float* __restrict__ bih0, const float* __restrict__ bhh0,
           const float* __restrict__ Wih1, const float* __restrict__ Whh1,
           const float* __restrict__ bih1, const float* __restrict__ bhh1,
           const float* __restrict__ Wih2, const float* __restrict__ Whh2,
           const float* __restrict__ bih2, const float* __restrict__ bhh2,
           const float* __restrict__ Wout, const float* __restrict__ bout,
           float* __restrict__ out)
{
    __shared__ __align__(16) float s_h[2][3][EPB][RS];   // [pingpong][layer][elem][unit]

    const int tid  = threadIdx.x;
    const int lane = tid & 31;
    const int warp = tid >> 5;
    const int g    = lane / 10;        // element slot within warp (3 for lanes 30,31)
    const int j    = lane - g * 10;    // hidden unit (valid index even for idle lanes)
    const int eb   = warp * EPW + g;
    const int e    = blockIdx.x * EPB + eb;
    const bool act = (lane < 30) && (e < B);

    for (int idx = tid; idx < 2 * 3 * EPB * RS; idx += WARPS * 32)
        (&s_h[0][0][0][0])[idx] = 0.0f;

    // ---- all weights in registers, dot-product operands packed as f32x2 ----
    float w0x[3][3];
    u64 w0h[3][5];
    u64 w1i[3][5], w1h[3][5];
    u64 w2i[3][5], w2h[3][5];
#pragma unroll
    for (int gg = 0; gg < 3; gg++) {
        const int row = gg * 10 + j;
#pragma unroll
        for (int k = 0; k < 3; k++) w0x[gg][k] = Wih0[row * 3 + k];
#pragma unroll
        for (int k = 0; k < 5; k++) {
            w0h[gg][k] = pack2(Whh0[row * 10 + 2 * k], Whh0[row * 10 + 2 * k + 1]);
            w1i[gg][k] = pack2(Wih1[row * 10 + 2 * k], Wih1[row * 10 + 2 * k + 1]);
            w1h[gg][k] = pack2(Whh1[row * 10 + 2 * k], Whh1[row * 10 + 2 * k + 1]);
            w2i[gg][k] = pack2(Wih2[row * 10 + 2 * k], Wih2[row * 10 + 2 * k + 1]);
            w2h[gg][k] = pack2(Whh2[row * 10 + 2 * k], Whh2[row * 10 + 2 * k + 1]);
        }
    }
    // Biases folded and packed (bias in lo half, 0 in hi half).
    const u64 b0R  = pack2(bih0[j] + bhh0[j], 0.f);
    const u64 b0Z  = pack2(bih0[10 + j] + bhh0[10 + j], 0.f);
    const u64 b0HN = pack2(bhh0[20 + j], 0.f);
    const float b0XN = bih0[20 + j];
    const u64 b1R  = pack2(bih1[j] + bhh1[j], 0.f);
    const u64 b1Z  = pack2(bih1[10 + j] + bhh1[10 + j], 0.f);
    const u64 b1XN = pack2(bih1[20 + j], 0.f);
    const u64 b1HN = pack2(bhh1[20 + j], 0.f);
    const u64 b2R  = pack2(bih2[j] + bhh2[j], 0.f);
    const u64 b2Z  = pack2(bih2[10 + j] + bhh2[10 + j], 0.f);
    const u64 b2XN = pack2(bih2[20 + j], 0.f);
    const u64 b2HN = pack2(bhh2[20 + j], 0.f);

    __syncthreads();

    const float* xe = x + (long)e * (T * IN);
    float xa0 = 0.f, xa1 = 0.f, xa2 = 0.f;
    if (act) { xa0 = xe[0]; xa1 = xe[1]; xa2 = xe[2]; }

    float myh0 = 0.f, myh1 = 0.f, myh2 = 0.f;

#pragma unroll 2
    for (int t = 0; t < T; ++t) {
        const int ob = t & 1;      // read buffer (h at t-1)
        const int nb = ob ^ 1;     // write buffer (h at t)

        // Prefetch next timestep's x.
        float xb0 = 0.f, xb1 = 0.f, xb2 = 0.f;
        if (act) {
            int tn = (t + 1 < T) ? (t + 1) : t;
            const float* p = xe + tn * IN;
            xb0 = p[0]; xb1 = p[1]; xb2 = p[2];
        }

        // ---- layer 0 (input width 3 scalar, h part packed) ----
        if (act) {
            u64 hv[5];
            load10p(&s_h[ob][0][eb][0], hv);
            u64 aR = b0R, aZ = b0Z, aHN = b0HN;
#pragma unroll
            for (int k = 0; k < 5; k++) {
                aR  = fma2(w0h[0][k], hv[k], aR);
                aZ  = fma2(w0h[1][k], hv[k], aZ);
                aHN = fma2(w0h[2][k], hv[k], aHN);
            }
            float xr  = fmaf(w0x[0][2], xa2, fmaf(w0x[0][1], xa1, w0x[0][0] * xa0));
            float xz  = fmaf(w0x[1][2], xa2, fmaf(w0x[1][1], xa1, w0x[1][0] * xa0));
            float axn = fmaf(w0x[2][2], xa2, fmaf(w0x[2][1], xa1, fmaf(w0x[2][0], xa0, b0XN)));
            float r = sigf(hsum2(aR) + xr);
            float z = sigf(hsum2(aZ) + xz);
            float n = tanhf_fast(fmaf(r, hsum2(aHN), axn));
            myh0 = n + z * (myh0 - n);
            s_h[nb][0][eb][j] = myh0;
        }
        __syncwarp();

        // ---- layer 1 ----
        if (act) {
            u64 iv[5], hv[5];
            load10p(&s_h[nb][0][eb][0], iv);
            load10p(&s_h[ob][1][eb][0], hv);
            myh1 = cell(w1i, w1h, b1R, b1Z, b1XN, b1HN, iv, hv, myh1);
            s_h[nb][1][eb][j] = myh1;
        }
        __syncwarp();

        // ---- layer 2 ----
        if (act) {
            u64 iv[5], hv[5];
            load10p(&s_h[nb][1][eb][0], iv);
            load10p(&s_h[ob][2][eb][0], hv);
            myh2 = cell(w2i, w2h, b2R, b2Z, b2XN, b2HN, iv, hv, myh2);
            s_h[nb][2][eb][j] = myh2;
        }
        __syncwarp();

        xa0 = xb0; xa1 = xb1; xa2 = xb2;
    }

    // Output head: out[e] = Wout . h2_final + bout (final h2 is in buffer T&1 = 0)
    if (act && j == 0) {
        const float* hp = &s_h[T & 1][2][eb][0];
        float acc = bout[0];
#pragma unroll
        for (int k = 0; k < 10; k++) acc = fmaf(Wout[k], hp[k], acc);
        out[e] = acc;
    }
}

} // namespace

extern "C" void kernel_launch(void* const* d_in, const int* in_sizes, int n_in,
                              void* d_out, int out_size) {
    const float* x    = (const float*)d_in[0];
    const float* Wih0 = (const float*)d_in[1];
    const float* Whh0 = (const float*)d_in[2];
    const float* bih0 = (const float*)d_in[3];
    const float* bhh0 = (const float*)d_in[4];
    const float* Wih1 = (const float*)d_in[5];
    const float* Whh1 = (const float*)d_in[6];
    const float* bih1 = (const float*)d_in[7];
    const float* bhh1 = (const float*)d_in[8];
    const float* Wih2 = (const float*)d_in[9];
    const float* Whh2 = (const float*)d_in[10];
    const float* bih2 = (const float*)d_in[11];
    const float* bhh2 = (const float*)d_in[12];
    const float* Wout = (const float*)d_in[13];
    const float* bout = (const float*)d_in[14];
    float* out = (float*)d_out;

    gru3_fused<<<NBLK, WARPS * 32>>>(x, Wih0, Whh0, bih0, bhh0,
                                     Wih1, Whh1, bih1, bhh1,
                                     Wih2, Whh2, bih2, bhh2,
                                     Wout, bout, out);
}

// round 4
// speedup vs baseline: 1.4617x; 1.3411x over previous
#include <cuda_runtime.h>

namespace {

using u64 = unsigned long long;

constexpr int B  = 4096;
constexpr int T  = 1000;
constexpr int IN = 3;

constexpr int WARPS = 4;            // warps per block
constexpr int EPW   = 3;            // elements per warp (30 active lanes)
constexpr int EPB   = WARPS * EPW;  // 12 elements per block
constexpr int NBLK  = (B + EPB - 1) / EPB;  // 342 -> 3 blocks/SM, single wave
constexpr int RS    = 12;           // padded row stride (floats), 48B (16B-aligned rows)

// ---- packed f32x2 helpers ----
__device__ __forceinline__ u64 fma2(u64 a, u64 b, u64 c) {
    u64 d;
    asm("fma.rn.f32x2 %0, %1, %2, %3;" : "=l"(d) : "l"(a), "l"(b), "l"(c));
    return d;
}
__device__ __forceinline__ u64 pack2(float lo, float hi) {
    u64 d;
    asm("mov.b64 %0, {%1, %2};" : "=l"(d) : "f"(lo), "f"(hi));
    return d;
}
__device__ __forceinline__ float hsum2b(u64 v, float b) {
    float lo, hi;
    asm("mov.b64 {%0, %1}, %2;" : "=f"(lo), "=f"(hi) : "l"(v));
    return (lo + hi) + b;
}

// MUFU.TANH — single-SFU activation
__device__ __forceinline__ float tanhapx(float v) {
    float y;
    asm("tanh.approx.f32 %0, %1;" : "=f"(y) : "f"(v));
    return y;
}
// sigmoid(x) where a = x/2 already (0.5 folded into weights/biases at init)
__device__ __forceinline__ float sighalf(float a) {
    return fmaf(0.5f, tanhapx(a), 0.5f);
}

// Load a 10-float smem row (16B-aligned, RS=12 padding) as 5 packed f32x2 values.
__device__ __forceinline__ void load10p(const float* __restrict__ p, u64* v) {
    ulonglong2 a = *reinterpret_cast<const ulonglong2*>(p);
    ulonglong2 b = *reinterpret_cast<const ulonglong2*>(p + 4);
    v[0] = a.x; v[1] = a.y; v[2] = b.x; v[3] = b.y;
    v[4] = *reinterpret_cast<const u64*>(p + 8);
}

// GRU cell, weights as packed register arrays. r/z rows pre-scaled by 0.5.
__device__ __forceinline__ float cell_reg(
    const u64 (&wi)[3][5], const u64 (&wh)[3][5],
    float bR, float bZ, float bXN, float bHN,
    const u64* __restrict__ iv, const u64* __restrict__ hv, float h)
{
    u64 aR = 0ull, aZ = 0ull, aN = 0ull, aH = 0ull;
#pragma unroll
    for (int k = 0; k < 5; k++) {
        aR = fma2(wi[0][k], iv[k], aR);
        aZ = fma2(wi[1][k], iv[k], aZ);
        aN = fma2(wi[2][k], iv[k], aN);
    }
#pragma unroll
    for (int k = 0; k < 5; k++) {
        aR = fma2(wh[0][k], hv[k], aR);
        aZ = fma2(wh[1][k], hv[k], aZ);
        aH = fma2(wh[2][k], hv[k], aH);
    }
    float r = sighalf(hsum2b(aR, bR));
    float z = sighalf(hsum2b(aZ, bZ));
    float n = tanhapx(fmaf(r, hsum2b(aH, bHN), hsum2b(aN, bXN)));
    return n + z * (h - n);
}

__global__ void __launch_bounds__(WARPS * 32, 3)
gru3_fused(const float* __restrict__ x,
           const float* __restrict__ Wih0, const float* __restrict__ Whh0,
           const float* __restrict__ bih0, const float* __restrict__ bhh0,
           const float* __restrict__ Wih1, const float* __restrict__ Whh1,
           const float* __restrict__ bih1, const float* __restrict__ bhh1,
           const float* __restrict__ Wih2, const float* __restrict__ Whh2,
           const float* __restrict__ bih2, const float* __restrict__ bhh2,
           const float* __restrict__ Wout, const float* __restrict__ bout,
           float* __restrict__ out)
{
    __shared__ __align__(16) float s_w2i[30 * RS], s_w2h[30 * RS];
    __shared__ __align__(16) float s_h[2][3][EPB][RS];   // [pingpong][layer][elem][unit]

    const int tid  = threadIdx.x;
    const int lane = tid & 31;
    const int warp = tid >> 5;
    const int g    = lane / 10;        // element slot within warp
    const int j    = lane - g * 10;    // hidden unit
    const int eb   = warp * EPW + g;
    const int e    = blockIdx.x * EPB + eb;
    const bool act = (lane < 30) && (e < B);

    // Stage layer-2 weights into padded smem rows; pre-scale r/z rows by 0.5.
    for (int idx = tid; idx < 300; idx += WARPS * 32) {
        int r = idx / 10, c = idx - r * 10;
        float s = (r < 20) ? 0.5f : 1.0f;
        s_w2i[r * RS + c] = Wih2[idx] * s;
        s_w2h[r * RS + c] = Whh2[idx] * s;
    }
    for (int idx = tid; idx < 2 * 3 * EPB * RS; idx += WARPS * 32)
        (&s_h[0][0][0][0])[idx] = 0.0f;

    // ---- layer-0 / layer-1 weights in registers (r/z rows pre-scaled by 0.5) ----
    float w0x[3][3];
    u64 w0h[3][5], w1i[3][5], w1h[3][5];
#pragma unroll
    for (int gg = 0; gg < 3; gg++) {
        const int row = gg * 10 + j;
        const float s = (gg < 2) ? 0.5f : 1.0f;
#pragma unroll
        for (int k = 0; k < 3; k++) w0x[gg][k] = Wih0[row * 3 + k] * s;
#pragma unroll
        for (int k = 0; k < 5; k++) {
            w0h[gg][k] = pack2(Whh0[row * 10 + 2 * k] * s, Whh0[row * 10 + 2 * k + 1] * s);
            w1i[gg][k] = pack2(Wih1[row * 10 + 2 * k] * s, Wih1[row * 10 + 2 * k + 1] * s);
            w1h[gg][k] = pack2(Whh1[row * 10 + 2 * k] * s, Whh1[row * 10 + 2 * k + 1] * s);
        }
    }
    // Scalar biases (r/z halved to match folded sigmoid pre-scale).
    const float b0R  = 0.5f * (bih0[j] + bhh0[j]);
    const float b0Z  = 0.5f * (bih0[10 + j] + bhh0[10 + j]);
    const float b0XN = bih0[20 + j];
    const float b0HN = bhh0[20 + j];
    const float b1R  = 0.5f * (bih1[j] + bhh1[j]);
    const float b1Z  = 0.5f * (bih1[10 + j] + bhh1[10 + j]);
    const float b1XN = bih1[20 + j];
    const float b1HN = bhh1[20 + j];
    const float b2R  = 0.5f * (bih2[j] + bhh2[j]);
    const float b2Z  = 0.5f * (bih2[10 + j] + bhh2[10 + j]);
    const float b2XN = bih2[20 + j];
    const float b2HN = bhh2[20 + j];

    // Loop-invariant layer-2 smem row pointers.
    const float* w2i_r = s_w2i + j * RS;
    const float* w2i_z = s_w2i + (10 + j) * RS;
    const float* w2i_n = s_w2i + (20 + j) * RS;
    const float* w2h_r = s_w2h + j * RS;
    const float* w2h_z = s_w2h + (10 + j) * RS;
    const float* w2h_n = s_w2h + (20 + j) * RS;

    __syncthreads();

    const float* xe = x + (long)e * (T * IN);
    float xa0 = 0.f, xa1 = 0.f, xa2 = 0.f;
    if (act) { xa0 = xe[0]; xa1 = xe[1]; xa2 = xe[2]; }

    float myh0 = 0.f, myh1 = 0.f, myh2 = 0.f;

#pragma unroll 2
    for (int t = 0; t < T; ++t) {
        const int ob = t & 1;      // read buffer (h at t-1)
        const int nb = ob ^ 1;     // write buffer (h at t)

        // Prefetch next timestep's x.
        float xb0 = 0.f, xb1 = 0.f, xb2 = 0.f;
        if (act) {
            int tn = (t + 1 < T) ? (t + 1) : t;
            const float* p = xe + tn * IN;
            xb0 = p[0]; xb1 = p[1]; xb2 = p[2];
        }

        // ---- layer 0 (input width 3 scalar, h part packed; weights in regs) ----
        if (act) {
            u64 hv[5];
            load10p(&s_h[ob][0][eb][0], hv);
            u64 aR = 0ull, aZ = 0ull, aH = 0ull;
#pragma unroll
            for (int k = 0; k < 5; k++) {
                aR = fma2(w0h[0][k], hv[k], aR);
                aZ = fma2(w0h[1][k], hv[k], aZ);
                aH = fma2(w0h[2][k], hv[k], aH);
            }
            float xr  = fmaf(w0x[0][2], xa2, fmaf(w0x[0][1], xa1, fmaf(w0x[0][0], xa0, b0R)));
            float xz  = fmaf(w0x[1][2], xa2, fmaf(w0x[1][1], xa1, fmaf(w0x[1][0], xa0, b0Z)));
            float axn = fmaf(w0x[2][2], xa2, fmaf(w0x[2][1], xa1, fmaf(w0x[2][0], xa0, b0XN)));
            float r = sighalf(hsum2b(aR, xr));
            float z = sighalf(hsum2b(aZ, xz));
            float n = tanhapx(fmaf(r, hsum2b(aH, b0HN), axn));
            myh0 = n + z * (myh0 - n);
            s_h[nb][0][eb][j] = myh0;
        }
        __syncwarp();

        // ---- layer 1 (weights in regs) ----
        if (act) {
            u64 iv[5], hv[5];
            load10p(&s_h[nb][0][eb][0], iv);
            load10p(&s_h[ob][1][eb][0], hv);
            myh1 = cell_reg(w1i, w1h, b1R, b1Z, b1XN, b1HN, iv, hv, myh1);
            s_h[nb][1][eb][j] = myh1;
        }
        __syncwarp();

        // ---- layer 2 (weights from smem rows) ----
        if (act) {
            u64 iv[5], hv[5];
            load10p(&s_h[nb][1][eb][0], iv);
            load10p(&s_h[ob][2][eb][0], hv);
            u64 wi[3][5], wh[3][5];
            load10p(w2i_r, wi[0]); load10p(w2i_z, wi[1]); load10p(w2i_n, wi[2]);
            load10p(w2h_r, wh[0]); load10p(w2h_z, wh[1]); load10p(w2h_n, wh[2]);
            myh2 = cell_reg(wi, wh, b2R, b2Z, b2XN, b2HN, iv, hv, myh2);
            s_h[nb][2][eb][j] = myh2;
        }
        __syncwarp();

        xa0 = xb0; xa1 = xb1; xa2 = xb2;
    }

    // Output head: out[e] = Wout . h2_final + bout (final h2 is in buffer T&1 = 0)
    if (act && j == 0) {
        const float* hp = &s_h[T & 1][2][eb][0];
        float acc = bout[0];
#pragma unroll
        for (int k = 0; k < 10; k++) acc = fmaf(Wout[k], hp[k], acc);
        out[e] = acc;
    }
}

} // namespace

extern "C" void kernel_launch(void* const* d_in, const int* in_sizes, int n_in,
                              void* d_out, int out_size) {
    const float* x    = (const float*)d_in[0];
    const float* Wih0 = (const float*)d_in[1];
    const float* Whh0 = (const float*)d_in[2];
    const float* bih0 = (const float*)d_in[3];
    const float* bhh0 = (const float*)d_in[4];
    const float* Wih1 = (const float*)d_in[5];
    const float* Whh1 = (const float*)d_in[6];
    const float* bih1 = (const float*)d_in[7];
    const float* bhh1 = (const float*)d_in[8];
    const float* Wih2 = (const float*)d_in[9];
    const float* Whh2 = (const float*)d_in[10];
    const float* bih2 = (const float*)d_in[11];
    const float* bhh2 = (const float*)d_in[12];
    const float* Wout = (const float*)d_in[13];
    const float* bout = (const float*)d_in[14];
    float* out = (float*)d_out;

    gru3_fused<<<NBLK, WARPS * 32>>>(x, Wih0, Whh0, bih0, bhh0,
                                     Wih1, Whh1, bih1, bhh1,
                                     Wih2, Whh2, bih2, bhh2,
                                     Wout, bout, out);
}